// round 15
// baseline (speedup 1.0000x reference)
#include <cuda_runtime.h>
#include <cuda_fp16.h>
#include <math.h>
#include <stdint.h>

#define B_ 2
#define S_ 2048
#define D_ 2048
#define H_ 16
#define KVH_ 4
#define HD_ 128
#define REP_ (H_/KVH_)
#define QKV_N 3072          // 2048 Q | 512 K | 512 V
#define SCLF 0.12752934082f  // log2e / sqrt(128)

// Scratch (device globals: allocation-free)
__device__ __half g_xh   [B_*S_*D_];
__device__ __half g_wqkv [QKV_N*D_];       // [N,K] fused Q|K|V weights
__device__ __half g_woh  [D_*H_*HD_];      // [N,K]
__device__ __half g_qkv  [B_*S_*QKV_N];    // fused projections
__device__ __half g_attn [B_*S_*H_*HD_];
__device__ float2 g_ropetab[S_*64];

// ---------------------------------------------------------------------------
// helpers
// ---------------------------------------------------------------------------
__device__ __forceinline__ float ex2f(float x) {
    float r;
    asm("ex2.approx.ftz.f32 %0, %1;" : "=f"(r) : "f"(x));
    return r;
}
__device__ __forceinline__ void mma_f16(
    float* c, const unsigned* a, const unsigned* b)
{
    asm volatile(
        "mma.sync.aligned.m16n8k16.row.col.f32.f16.f16.f32 "
        "{%0,%1,%2,%3}, {%4,%5,%6,%7}, {%8,%9}, {%0,%1,%2,%3};"
        : "+f"(c[0]), "+f"(c[1]), "+f"(c[2]), "+f"(c[3])
        : "r"(a[0]), "r"(a[1]), "r"(a[2]), "r"(a[3]),
          "r"(b[0]), "r"(b[1]));
}
__device__ __forceinline__ void cp16(void* s, const void* g) {
    unsigned sa = (unsigned)__cvta_generic_to_shared(s);
    asm volatile("cp.async.cg.shared.global [%0], [%1], 16;" :: "r"(sa), "l"(g));
}
#define CP_COMMIT()  asm volatile("cp.async.commit_group;")
#define CP_WAIT(n)   asm volatile("cp.async.wait_group %0;" :: "n"(n))

__device__ __forceinline__ void ldmx4(
    unsigned& r0, unsigned& r1, unsigned& r2, unsigned& r3, unsigned addr)
{
    asm volatile(
        "ldmatrix.sync.aligned.m8n8.x4.shared.b16 {%0,%1,%2,%3}, [%4];"
        : "=r"(r0), "=r"(r1), "=r"(r2), "=r"(r3) : "r"(addr));
}
__device__ __forceinline__ void ldmx4_trans(
    unsigned& r0, unsigned& r1, unsigned& r2, unsigned& r3, unsigned addr)
{
    asm volatile(
        "ldmatrix.sync.aligned.m8n8.x4.trans.shared.b16 {%0,%1,%2,%3}, [%4];"
        : "=r"(r0), "=r"(r1), "=r"(r2), "=r"(r3) : "r"(addr));
}
__device__ __forceinline__ unsigned pack_h2(float lo, float hi) {
    __half2 h = __floats2half2_rn(lo, hi);
    return *reinterpret_cast<unsigned*>(&h);
}

// ---------------------------------------------------------------------------
// prep (ONE launch, block 32x8):
//  y 0..159   : weight transposes (Wq/Wk/Wv/Wo -> [N,K] fp16)
//  y 160..295 : lin = (y-160)*64 + x : 0..8191 x-convert, 8192..8703 rope table
// ---------------------------------------------------------------------------
__global__ void prep_all_kernel(const float* __restrict__ x,
                                const float* __restrict__ Wq,
                                const float* __restrict__ Wk,
                                const float* __restrict__ Wv,
                                const float* __restrict__ Wo)
{
    const int yb = blockIdx.y;
    if (yb < 160) {
        __shared__ float t[32][33];
        const float* in; __half* out; int N; int n0;
        if (yb < 64)       { in = Wq; out = g_wqkv;             N = 2048; n0 = yb * 32; }
        else if (yb < 80)  { in = Wk; out = g_wqkv + 2048 * D_; N = 512;  n0 = (yb - 64) * 32; }
        else if (yb < 96)  { in = Wv; out = g_wqkv + 2560 * D_; N = 512;  n0 = (yb - 80) * 32; }
        else               { in = Wo; out = g_woh;              N = 2048; n0 = (yb - 96) * 32; }
        const int k0 = blockIdx.x * 32;
        const int tx = threadIdx.x, ty = threadIdx.y;
        #pragma unroll
        for (int i = 0; i < 32; i += 8)
            t[ty + i][tx] = in[(long)(k0 + ty + i) * N + n0 + tx];
        __syncthreads();
        #pragma unroll
        for (int i = 0; i < 32; i += 8)
            out[(long)(n0 + ty + i) * 2048 + k0 + tx] = __float2half_rn(t[tx][ty + i]);
    } else {
        const int lin = (yb - 160) * 64 + blockIdx.x;       // 0..8703
        const int tid = threadIdx.y * 32 + threadIdx.x;
        if (lin < 8192) {
            int i = lin * 256 + tid;                        // < B*S*D/4
            float4 v = reinterpret_cast<const float4*>(x)[i];
            uint2 u;
            u.x = pack_h2(v.x, v.y);
            u.y = pack_h2(v.z, v.w);
            reinterpret_cast<uint2*>(g_xh)[i] = u;
        } else {
            int id = (lin - 8192) * 256 + tid;              // < S*64
            int s = id >> 6, i = id & 63;
            float inv = exp2f(-(float)i * (13.287712379549449f / 64.0f));
            float sn, cs;
            sincosf((float)s * inv, &sn, &cs);
            g_ropetab[id] = make_float2(cs, sn);
        }
    }
}

// ---------------------------------------------------------------------------
// RoPE over fused qkv: 20 rotated heads (16 Q + 4 K); Q additionally scaled
// by log2e/sqrt(HD). Each thread: 4 consecutive rotation lanes (uint2 I/O).
// ---------------------------------------------------------------------------
__global__ void rope_qkv_kernel()
{
    long idx = (long)blockIdx.x * blockDim.x + threadIdx.x;  // M*20*16 threads
    int i4 = (int)(idx & 15) * 4;
    long t = idx >> 4;
    int h20 = (int)(t % 20);
    long row = t / 20;
    int s = (int)(row % S_);

    const float scl = (h20 < 16) ? SCLF : 1.0f;
    const int col = (h20 < 16) ? h20 * 128 : 2048 + (h20 - 16) * 128;
    __half* p = g_qkv + row * QKV_N + col;

    uint2 lo = *reinterpret_cast<uint2*>(p + i4);
    uint2 hi = *reinterpret_cast<uint2*>(p + i4 + 64);
    const __half2* lo2 = reinterpret_cast<const __half2*>(&lo);
    const __half2* hi2 = reinterpret_cast<const __half2*>(&hi);

    uint2 olo, ohi;
    unsigned* polo = reinterpret_cast<unsigned*>(&olo);
    unsigned* pohi = reinterpret_cast<unsigned*>(&ohi);
    #pragma unroll
    for (int j = 0; j < 2; j++) {
        float2 ta = g_ropetab[s * 64 + i4 + 2*j];
        float2 tb = g_ropetab[s * 64 + i4 + 2*j + 1];
        float x1a = __low2float(lo2[j]),  x1b = __high2float(lo2[j]);
        float x2a = __low2float(hi2[j]),  x2b = __high2float(hi2[j]);
        polo[j] = pack_h2((x1a * ta.x - x2a * ta.y) * scl,
                          (x1b * tb.x - x2b * tb.y) * scl);
        pohi[j] = pack_h2((x2a * ta.x + x1a * ta.y) * scl,
                          (x2b * tb.x + x1b * tb.y) * scl);
    }
    *reinterpret_cast<uint2*>(p + i4)      = olo;
    *reinterpret_cast<uint2*>(p + i4 + 64) = ohi;
}

// ---------------------------------------------------------------------------
// FP16 GEMM: C[M,N] = A[M,K] @ Bt[N,K]^T, fp32 accum, ldmatrix fragments.
// 256 threads (8 warps 2x4), CTA tile 128x128, BK=64, 3-stage cp.async ring.
// ---------------------------------------------------------------------------
#define HT_BYTES (128*128)
#define HNS 3
#define HSM_TOTAL (2*HNS*HT_BYTES)   // 98304

template<bool HOUT>
__global__ __launch_bounds__(256) void h_gemm_kernel(
    const __half* __restrict__ A, const __half* __restrict__ Bt,
    void* __restrict__ Cv, int M, int N, int K)
{
    extern __shared__ char smem[];
    char* AsBase = smem;
    char* BsBase = smem + HNS * HT_BYTES;
    const unsigned smem32 = (unsigned)__cvta_generic_to_shared(smem);

    const int tid  = threadIdx.x;
    const int lane = tid & 31;
    const int warp = tid >> 5;
    const int wm   = warp >> 2;
    const int wn   = warp & 3;
    const int bm   = blockIdx.y * 128;
    const int bn   = blockIdx.x * 128;
    const int lq = lane >> 2;
    const int lr = lane & 3;

    const int a_rl = (lane & 7) + ((lane & 8) ? 8 : 0);
    const int a_ch = lane >> 4;
    const int b_rl = (lane & 7) + ((lane & 16) ? 8 : 0);
    const int b_ch = (lane >> 3) & 1;

    float acc[4][4][4];
    #pragma unroll
    for (int mt = 0; mt < 4; mt++)
        #pragma unroll
        for (int nt = 0; nt < 4; nt++)
            #pragma unroll
            for (int i = 0; i < 4; i++) acc[mt][nt][i] = 0.f;

    const int NK = K >> 6;

    auto fill = [&](int j, int s) {
        char* As = AsBase + s * HT_BYTES;
        char* Bs = BsBase + s * HT_BYTES;
        const __half* Ag = A  + (long)bm * K + j * 64;
        const __half* Bg = Bt + (long)bn * K + j * 64;
        #pragma unroll
        for (int l = 0; l < 4; l++) {
            int idx = tid + l * 256;
            int r = idx >> 3, c8 = idx & 7;
            int dst = r * 128 + ((c8 ^ (r & 7)) << 4);
            cp16(As + dst, Ag + (long)r * K + c8 * 8);
            cp16(Bs + dst, Bg + (long)r * K + c8 * 8);
        }
        CP_COMMIT();
    };

    fill(0, 0);
    if (NK > 1) fill(1, 1);

    int arow[4], brow[2];
    #pragma unroll
    for (int mt = 0; mt < 4; mt++) arow[mt] = wm * 64 + mt * 16 + a_rl;
    #pragma unroll
    for (int p = 0; p < 2; p++) brow[p] = wn * 32 + p * 16 + b_rl;

    for (int it = 0; it < NK; it++) {
        if (it + 1 < NK) { CP_WAIT(1); } else { CP_WAIT(0); }
        __syncthreads();
        if (it + 2 < NK) fill(it + 2, (it + 2) % 3);

        const unsigned Ab = smem32 + (it % 3) * HT_BYTES;
        const unsigned Bb = smem32 + (HNS + it % 3) * HT_BYTES;

        #pragma unroll
        for (int ks = 0; ks < 4; ks++) {
            unsigned a[4][4], b[4][2];
            #pragma unroll
            for (int mt = 0; mt < 4; mt++) {
                int ch = 2 * ks + a_ch;
                unsigned addr = Ab + arow[mt] * 128 + ((ch ^ (arow[mt] & 7)) << 4);
                ldmx4(a[mt][0], a[mt][1], a[mt][2], a[mt][3], addr);
            }
            #pragma unroll
            for (int p = 0; p < 2; p++) {
                int ch = 2 * ks + b_ch;
                unsigned addr = Bb + brow[p] * 128 + ((ch ^ (brow[p] & 7)) << 4);
                ldmx4(b[2*p][0], b[2*p][1], b[2*p+1][0], b[2*p+1][1], addr);
            }
            #pragma unroll
            for (int mt = 0; mt < 4; mt++)
                #pragma unroll
                for (int nt = 0; nt < 4; nt++)
                    mma_f16(acc[mt][nt], a[mt], b[nt]);
        }
    }

    #pragma unroll
    for (int mt = 0; mt < 4; mt++) {
        long row0 = bm + wm * 64 + mt * 16 + lq;
        long row1 = row0 + 8;
        #pragma unroll
        for (int nt = 0; nt < 4; nt++) {
            int col = bn + wn * 32 + nt * 8 + 2 * lr;
            if (HOUT) {
                __half* C = (__half*)Cv;
                *reinterpret_cast<unsigned*>(&C[row0 * N + col]) =
                    pack_h2(acc[mt][nt][0], acc[mt][nt][1]);
                *reinterpret_cast<unsigned*>(&C[row1 * N + col]) =
                    pack_h2(acc[mt][nt][2], acc[mt][nt][3]);
            } else {
                float* C = (float*)Cv;
                *reinterpret_cast<float2*>(&C[row0 * N + col]) =
                    make_float2(acc[mt][nt][0], acc[mt][nt][1]);
                *reinterpret_cast<float2*>(&C[row1 * N + col]) =
                    make_float2(acc[mt][nt][2], acc[mt][nt][3]);
            }
        }
    }
}

// ---------------------------------------------------------------------------
// FP16 flash attention, K+V double-buffered, causal, 2 CTAs/SM target.
// Grid (S/128, H, B), 256 threads (8 warps), warp = 16 q rows.
// ONE barrier per kv-tile: WAIT(0) -> sync -> issue load(kt+1) -> compute kt.
// ---------------------------------------------------------------------------
#define AQ_OFF 0
#define AK_OFF 32768
#define AV_OFF 65536
#define AP_OFF 98304
#define ATTN_SMEM_BYTES 114688

__device__ __forceinline__ float red_max4(float v) {
    v = fmaxf(v, __shfl_xor_sync(0xffffffffu, v, 1));
    v = fmaxf(v, __shfl_xor_sync(0xffffffffu, v, 2));
    return v;
}
__device__ __forceinline__ float red_sum4(float v) {
    v += __shfl_xor_sync(0xffffffffu, v, 1);
    v += __shfl_xor_sync(0xffffffffu, v, 2);
    return v;
}
__device__ __forceinline__ int sw256(int r, int c16) {
    return (c16 & 8) | ((c16 ^ r) & 7);
}

__global__ __launch_bounds__(256, 2) void attn_h_kernel()
{
    extern __shared__ char smc[];
    char* Qs = smc + AQ_OFF;
    char* Ps = smc + AP_OFF;
    const unsigned smem32 = (unsigned)__cvta_generic_to_shared(smc);

    const int qt = (int)(gridDim.x - 1) - blockIdx.x;
    const int h  = blockIdx.y;
    const int b  = blockIdx.z;
    const int kvh = h / REP_;

    const int tid  = threadIdx.x;
    const int lane = tid & 31;
    const int w    = tid >> 5;
    const int lq   = lane >> 2;
    const int lr   = lane & 3;

    const int a_rl = (lane & 7) + ((lane & 8) ? 8 : 0);
    const int a_ch = lane >> 4;
    const int b_rl = (lane & 7) + ((lane & 16) ? 8 : 0);
    const int b_ch = (lane >> 3) & 1;

    const int nkt = 2 * qt + 2;

    const long rowbase = (long)(b * S_);
    const int qcol = h * 128;
    const int kcol = 2048 + kvh * 128;
    const int vcol = 2560 + kvh * 128;

    auto load_kv = [&](int t) {
        char* Kd = smc + AK_OFF + (t & 1) * 16384;
        char* Vd = smc + AV_OFF + (t & 1) * 16384;
        #pragma unroll
        for (int l = 0; l < 4; l++) {
            int i = tid + l * 256;
            int r = i >> 4, c16 = i & 15;
            int dst = r * 256 + (sw256(r & 7, c16) << 4);
            cp16(Kd + dst, &g_qkv[(rowbase + t * 64 + r) * QKV_N + kcol + c16 * 8]);
            cp16(Vd + dst, &g_qkv[(rowbase + t * 64 + r) * QKV_N + vcol + c16 * 8]);
        }
        CP_COMMIT();
    };

    #pragma unroll
    for (int l = 0; l < 8; l++) {
        int i = tid + l * 256;
        int r = i >> 4, c16 = i & 15;
        cp16(Qs + r * 256 + (sw256(r & 7, c16) << 4),
             &g_qkv[(rowbase + qt * 128 + r) * QKV_N + qcol + c16 * 8]);
    }
    load_kv(0);

    float o[16][4];
    #pragma unroll
    for (int nt = 0; nt < 16; nt++)
        #pragma unroll
        for (int j = 0; j < 4; j++) o[nt][j] = 0.f;
    float m0 = -1e30f, m1 = -1e30f, l0 = 0.f, l1 = 0.f;

    const int qrow = w * 16 + lq;
    const int aqrow = w * 16 + a_rl;
    const int vt = lane >> 3;
    const int vl = lane & 7;

    for (int kt = 0; kt < nkt; kt++) {
        CP_WAIT(0);        // group(kt) complete (only outstanding group)
        __syncthreads();   // visibility + all warps done reading slot (kt+1)&1
        if (kt + 1 < nkt) load_kv(kt + 1);   // overlaps compute(kt)

        const unsigned Kb = smem32 + AK_OFF + (kt & 1) * 16384;
        const unsigned Vb = smem32 + AV_OFF + (kt & 1) * 16384;
        const unsigned Qb = smem32 + AQ_OFF;

        // ---- scores: S = Q K^T (already log2e-scaled via Q) ----
        float sacc[8][4];
        #pragma unroll
        for (int nt = 0; nt < 8; nt++)
            #pragma unroll
            for (int j = 0; j < 4; j++) sacc[nt][j] = 0.f;

        #pragma unroll
        for (int ks = 0; ks < 8; ks++) {
            unsigned a[4];
            {
                int ch = 2 * ks + a_ch;
                unsigned addr = Qb + aqrow * 256 + (sw256(aqrow & 7, ch) << 4);
                ldmx4(a[0], a[1], a[2], a[3], addr);
            }
            #pragma unroll
            for (int p = 0; p < 4; p++) {
                int row = p * 16 + b_rl;
                int ch = 2 * ks + b_ch;
                unsigned addr = Kb + row * 256 + (sw256(row & 7, ch) << 4);
                unsigned b0[2], b1[2];
                ldmx4(b0[0], b0[1], b1[0], b1[1], addr);
                mma_f16(sacc[2*p],     a, b0);
                mma_f16(sacc[2*p + 1], a, b1);
            }
        }

        if (kt >= 2 * qt) {
            int r0 = qt * 128 + qrow;
            int r1 = r0 + 8;
            #pragma unroll
            for (int nt = 0; nt < 8; nt++) {
                int c = kt * 64 + nt * 8 + 2 * lr;
                if (c     > r0) sacc[nt][0] = -1e30f;
                if (c + 1 > r0) sacc[nt][1] = -1e30f;
                if (c     > r1) sacc[nt][2] = -1e30f;
                if (c + 1 > r1) sacc[nt][3] = -1e30f;
            }
        }

        // ---- online softmax (base-2) ----
        float mt0 = -1e30f, mt1 = -1e30f;
        #pragma unroll
        for (int nt = 0; nt < 8; nt++) {
            mt0 = fmaxf(mt0, fmaxf(sacc[nt][0], sacc[nt][1]));
            mt1 = fmaxf(mt1, fmaxf(sacc[nt][2], sacc[nt][3]));
        }
        mt0 = red_max4(mt0);
        mt1 = red_max4(mt1);
        float mn0 = fmaxf(m0, mt0), mn1 = fmaxf(m1, mt1);
        float alpha0 = ex2f(m0 - mn0), alpha1 = ex2f(m1 - mn1);

        float rs0 = 0.f, rs1 = 0.f;
        #pragma unroll
        for (int nt = 0; nt < 8; nt++) {
            sacc[nt][0] = ex2f(sacc[nt][0] - mn0);
            sacc[nt][1] = ex2f(sacc[nt][1] - mn0);
            sacc[nt][2] = ex2f(sacc[nt][2] - mn1);
            sacc[nt][3] = ex2f(sacc[nt][3] - mn1);
            rs0 += sacc[nt][0] + sacc[nt][1];
            rs1 += sacc[nt][2] + sacc[nt][3];
        }
        rs0 = red_sum4(rs0);
        rs1 = red_sum4(rs1);
        l0 = l0 * alpha0 + rs0;
        l1 = l1 * alpha1 + rs1;
        m0 = mn0; m1 = mn1;

        #pragma unroll
        for (int nt = 0; nt < 16; nt++) {
            o[nt][0] *= alpha0; o[nt][1] *= alpha0;
            o[nt][2] *= alpha1; o[nt][3] *= alpha1;
        }

        // ---- store P (per-warp private rows) ----
        #pragma unroll
        for (int nt = 0; nt < 8; nt++) {
            int sw = ((nt ^ lq) & 7) << 4;
            *reinterpret_cast<unsigned*>(Ps + qrow * 128 + sw + 4 * lr) =
                pack_h2(sacc[nt][0], sacc[nt][1]);
            *reinterpret_cast<unsigned*>(Ps + (qrow + 8) * 128 + sw + 4 * lr) =
                pack_h2(sacc[nt][2], sacc[nt][3]);
        }
        __syncwarp();

        // ---- O += P V ----
        const unsigned Pb = smem32 + AP_OFF;
        #pragma unroll
        for (int ks = 0; ks < 4; ks++) {
            unsigned a[4];
            {
                int ch = 2 * ks + a_ch;
                unsigned addr = Pb + aqrow * 128 + (((ch ^ (aqrow & 7)) & 7) << 4);
                ldmx4(a[0], a[1], a[2], a[3], addr);
            }
            const int vrow = ks * 16 + ((vt & 1) << 3) + vl;
            #pragma unroll
            for (int ntt = 0; ntt < 8; ntt++) {
                int c16 = 2 * ntt + (vt >> 1);
                unsigned addr = Vb + vrow * 256 + (sw256(vl, c16) << 4);
                unsigned v0, v1, v2, v3;
                ldmx4_trans(v0, v1, v2, v3, addr);
                unsigned b0[2] = {v0, v1};
                unsigned b1[2] = {v2, v3};
                mma_f16(o[2 * ntt],     a, b0);
                mma_f16(o[2 * ntt + 1], a, b1);
            }
        }
    }

    // ---- epilogue ----
    float inv0 = 1.0f / l0;
    float inv1 = 1.0f / l1;
    long base0 = (rowbase + qt * 128 + qrow) * (H_ * HD_) + h * HD_;
    long base1 = base0 + (long)8 * (H_ * HD_);
    #pragma unroll
    for (int nt = 0; nt < 16; nt++) {
        int c = nt * 8 + 2 * lr;
        *reinterpret_cast<unsigned*>(&g_attn[base0 + c]) =
            pack_h2(o[nt][0] * inv0, o[nt][1] * inv0);
        *reinterpret_cast<unsigned*>(&g_attn[base1 + c]) =
            pack_h2(o[nt][2] * inv1, o[nt][3] * inv1);
    }
}

// ---------------------------------------------------------------------------
extern "C" void kernel_launch(void* const* d_in, const int* in_sizes, int n_in,
                              void* d_out, int out_size)
{
    const float* x  = (const float*)d_in[0];
    const float* Wq = (const float*)d_in[1];
    const float* Wk = (const float*)d_in[2];
    const float* Wv = (const float*)d_in[3];
    const float* Wo = (const float*)d_in[4];
    float* out = (float*)d_out;

    __half *xh, *wqkv, *woh, *qkv, *attn;
    cudaGetSymbolAddress((void**)&xh,   g_xh);
    cudaGetSymbolAddress((void**)&wqkv, g_wqkv);
    cudaGetSymbolAddress((void**)&woh,  g_woh);
    cudaGetSymbolAddress((void**)&qkv,  g_qkv);
    cudaGetSymbolAddress((void**)&attn, g_attn);

    const int M = B_ * S_;   // 4096

    // all prep in ONE launch
    prep_all_kernel<<<dim3(64, 296), dim3(32, 8)>>>(x, Wq, Wk, Wv, Wo);

    cudaFuncSetAttribute(h_gemm_kernel<true>,
                         cudaFuncAttributeMaxDynamicSharedMemorySize, HSM_TOTAL);
    cudaFuncSetAttribute(h_gemm_kernel<false>,
                         cudaFuncAttributeMaxDynamicSharedMemorySize, HSM_TOTAL);

    // fused QKV projection
    h_gemm_kernel<true><<<dim3(QKV_N/128, M/128), 256, HSM_TOTAL>>>(
        xh, wqkv, qkv, M, QKV_N, D_);

    // RoPE (q + k heads), vectorized, Q pre-scaled
    rope_qkv_kernel<<<(M * 20 * 16)/256, 256>>>();

    // Flash attention (2 CTAs/SM)
    cudaFuncSetAttribute(attn_h_kernel,
                         cudaFuncAttributeMaxDynamicSharedMemorySize, ATTN_SMEM_BYTES);
    attn_h_kernel<<<dim3(S_/128, H_, B_), 256, ATTN_SMEM_BYTES>>>();

    // Output projection (fp32 out)
    h_gemm_kernel<false><<<dim3(D_/128, M/128), 256, HSM_TOTAL>>>(
        attn, woh, out, M, D_, D_);
}

// round 16
// speedup vs baseline: 1.0269x; 1.0269x over previous
#include <cuda_runtime.h>
#include <cuda_fp16.h>
#include <math.h>
#include <stdint.h>

#define B_ 2
#define S_ 2048
#define D_ 2048
#define H_ 16
#define KVH_ 4
#define HD_ 128
#define REP_ (H_/KVH_)
#define QKV_N 3072          // 2048 Q | 512 K | 512 V
#define SCLF 0.12752934082f  // log2e / sqrt(128)

// Scratch (device globals: allocation-free)
__device__ __half g_xh   [B_*S_*D_];
__device__ __half g_wqkv [QKV_N*D_];       // [N,K] fused Q|K|V weights
__device__ __half g_woh  [D_*H_*HD_];      // [N,K]
__device__ __half g_qkv  [B_*S_*QKV_N];    // fused projections
__device__ __half g_attn [B_*S_*H_*HD_];
__device__ float2 g_ropetab[S_*64];

// ---------------------------------------------------------------------------
// helpers
// ---------------------------------------------------------------------------
__device__ __forceinline__ float ex2f(float x) {
    float r;
    asm("ex2.approx.ftz.f32 %0, %1;" : "=f"(r) : "f"(x));
    return r;
}
__device__ __forceinline__ void mma_f16(
    float* c, const unsigned* a, const unsigned* b)
{
    asm volatile(
        "mma.sync.aligned.m16n8k16.row.col.f32.f16.f16.f32 "
        "{%0,%1,%2,%3}, {%4,%5,%6,%7}, {%8,%9}, {%0,%1,%2,%3};"
        : "+f"(c[0]), "+f"(c[1]), "+f"(c[2]), "+f"(c[3])
        : "r"(a[0]), "r"(a[1]), "r"(a[2]), "r"(a[3]),
          "r"(b[0]), "r"(b[1]));
}
__device__ __forceinline__ void cp16(void* s, const void* g) {
    unsigned sa = (unsigned)__cvta_generic_to_shared(s);
    asm volatile("cp.async.cg.shared.global [%0], [%1], 16;" :: "r"(sa), "l"(g));
}
#define CP_COMMIT()  asm volatile("cp.async.commit_group;")
#define CP_WAIT(n)   asm volatile("cp.async.wait_group %0;" :: "n"(n))

__device__ __forceinline__ void ldmx4(
    unsigned& r0, unsigned& r1, unsigned& r2, unsigned& r3, unsigned addr)
{
    asm volatile(
        "ldmatrix.sync.aligned.m8n8.x4.shared.b16 {%0,%1,%2,%3}, [%4];"
        : "=r"(r0), "=r"(r1), "=r"(r2), "=r"(r3) : "r"(addr));
}
__device__ __forceinline__ void ldmx4_trans(
    unsigned& r0, unsigned& r1, unsigned& r2, unsigned& r3, unsigned addr)
{
    asm volatile(
        "ldmatrix.sync.aligned.m8n8.x4.trans.shared.b16 {%0,%1,%2,%3}, [%4];"
        : "=r"(r0), "=r"(r1), "=r"(r2), "=r"(r3) : "r"(addr));
}
__device__ __forceinline__ unsigned pack_h2(float lo, float hi) {
    __half2 h = __floats2half2_rn(lo, hi);
    return *reinterpret_cast<unsigned*>(&h);
}

// ---------------------------------------------------------------------------
// prep (ONE launch, block 32x8)
// ---------------------------------------------------------------------------
__global__ void prep_all_kernel(const float* __restrict__ x,
                                const float* __restrict__ Wq,
                                const float* __restrict__ Wk,
                                const float* __restrict__ Wv,
                                const float* __restrict__ Wo)
{
    const int yb = blockIdx.y;
    if (yb < 160) {
        __shared__ float t[32][33];
        const float* in; __half* out; int N; int n0;
        if (yb < 64)       { in = Wq; out = g_wqkv;             N = 2048; n0 = yb * 32; }
        else if (yb < 80)  { in = Wk; out = g_wqkv + 2048 * D_; N = 512;  n0 = (yb - 64) * 32; }
        else if (yb < 96)  { in = Wv; out = g_wqkv + 2560 * D_; N = 512;  n0 = (yb - 80) * 32; }
        else               { in = Wo; out = g_woh;              N = 2048; n0 = (yb - 96) * 32; }
        const int k0 = blockIdx.x * 32;
        const int tx = threadIdx.x, ty = threadIdx.y;
        #pragma unroll
        for (int i = 0; i < 32; i += 8)
            t[ty + i][tx] = in[(long)(k0 + ty + i) * N + n0 + tx];
        __syncthreads();
        #pragma unroll
        for (int i = 0; i < 32; i += 8)
            out[(long)(n0 + ty + i) * 2048 + k0 + tx] = __float2half_rn(t[tx][ty + i]);
    } else {
        const int lin = (yb - 160) * 64 + blockIdx.x;       // 0..8703
        const int tid = threadIdx.y * 32 + threadIdx.x;
        if (lin < 8192) {
            int i = lin * 256 + tid;
            float4 v = reinterpret_cast<const float4*>(x)[i];
            uint2 u;
            u.x = pack_h2(v.x, v.y);
            u.y = pack_h2(v.z, v.w);
            reinterpret_cast<uint2*>(g_xh)[i] = u;
        } else {
            int id = (lin - 8192) * 256 + tid;
            int s = id >> 6, i = id & 63;
            float inv = exp2f(-(float)i * (13.287712379549449f / 64.0f));
            float sn, cs;
            sincosf((float)s * inv, &sn, &cs);
            g_ropetab[id] = make_float2(cs, sn);
        }
    }
}

// ---------------------------------------------------------------------------
// RoPE over fused qkv; Q pre-scaled by log2e/sqrt(HD).
// ---------------------------------------------------------------------------
__global__ void rope_qkv_kernel()
{
    long idx = (long)blockIdx.x * blockDim.x + threadIdx.x;
    int i4 = (int)(idx & 15) * 4;
    long t = idx >> 4;
    int h20 = (int)(t % 20);
    long row = t / 20;
    int s = (int)(row % S_);

    const float scl = (h20 < 16) ? SCLF : 1.0f;
    const int col = (h20 < 16) ? h20 * 128 : 2048 + (h20 - 16) * 128;
    __half* p = g_qkv + row * QKV_N + col;

    uint2 lo = *reinterpret_cast<uint2*>(p + i4);
    uint2 hi = *reinterpret_cast<uint2*>(p + i4 + 64);
    const __half2* lo2 = reinterpret_cast<const __half2*>(&lo);
    const __half2* hi2 = reinterpret_cast<const __half2*>(&hi);

    uint2 olo, ohi;
    unsigned* polo = reinterpret_cast<unsigned*>(&olo);
    unsigned* pohi = reinterpret_cast<unsigned*>(&ohi);
    #pragma unroll
    for (int j = 0; j < 2; j++) {
        float2 ta = g_ropetab[s * 64 + i4 + 2*j];
        float2 tb = g_ropetab[s * 64 + i4 + 2*j + 1];
        float x1a = __low2float(lo2[j]),  x1b = __high2float(lo2[j]);
        float x2a = __low2float(hi2[j]),  x2b = __high2float(hi2[j]);
        polo[j] = pack_h2((x1a * ta.x - x2a * ta.y) * scl,
                          (x1b * tb.x - x2b * tb.y) * scl);
        pohi[j] = pack_h2((x2a * ta.x + x1a * ta.y) * scl,
                          (x2b * tb.x + x1b * tb.y) * scl);
    }
    *reinterpret_cast<uint2*>(p + i4)      = olo;
    *reinterpret_cast<uint2*>(p + i4 + 64) = ohi;
}

// ---------------------------------------------------------------------------
// FP16 GEMM (unchanged from R14 winner)
// ---------------------------------------------------------------------------
#define HT_BYTES (128*128)
#define HNS 3
#define HSM_TOTAL (2*HNS*HT_BYTES)   // 98304

template<bool HOUT>
__global__ __launch_bounds__(256) void h_gemm_kernel(
    const __half* __restrict__ A, const __half* __restrict__ Bt,
    void* __restrict__ Cv, int M, int N, int K)
{
    extern __shared__ char smem[];
    char* AsBase = smem;
    char* BsBase = smem + HNS * HT_BYTES;
    const unsigned smem32 = (unsigned)__cvta_generic_to_shared(smem);

    const int tid  = threadIdx.x;
    const int lane = tid & 31;
    const int warp = tid >> 5;
    const int wm   = warp >> 2;
    const int wn   = warp & 3;
    const int bm   = blockIdx.y * 128;
    const int bn   = blockIdx.x * 128;
    const int lq = lane >> 2;
    const int lr = lane & 3;

    const int a_rl = (lane & 7) + ((lane & 8) ? 8 : 0);
    const int a_ch = lane >> 4;
    const int b_rl = (lane & 7) + ((lane & 16) ? 8 : 0);
    const int b_ch = (lane >> 3) & 1;

    float acc[4][4][4];
    #pragma unroll
    for (int mt = 0; mt < 4; mt++)
        #pragma unroll
        for (int nt = 0; nt < 4; nt++)
            #pragma unroll
            for (int i = 0; i < 4; i++) acc[mt][nt][i] = 0.f;

    const int NK = K >> 6;

    auto fill = [&](int j, int s) {
        char* As = AsBase + s * HT_BYTES;
        char* Bs = BsBase + s * HT_BYTES;
        const __half* Ag = A  + (long)bm * K + j * 64;
        const __half* Bg = Bt + (long)bn * K + j * 64;
        #pragma unroll
        for (int l = 0; l < 4; l++) {
            int idx = tid + l * 256;
            int r = idx >> 3, c8 = idx & 7;
            int dst = r * 128 + ((c8 ^ (r & 7)) << 4);
            cp16(As + dst, Ag + (long)r * K + c8 * 8);
            cp16(Bs + dst, Bg + (long)r * K + c8 * 8);
        }
        CP_COMMIT();
    };

    fill(0, 0);
    if (NK > 1) fill(1, 1);

    int arow[4], brow[2];
    #pragma unroll
    for (int mt = 0; mt < 4; mt++) arow[mt] = wm * 64 + mt * 16 + a_rl;
    #pragma unroll
    for (int p = 0; p < 2; p++) brow[p] = wn * 32 + p * 16 + b_rl;

    for (int it = 0; it < NK; it++) {
        if (it + 1 < NK) { CP_WAIT(1); } else { CP_WAIT(0); }
        __syncthreads();
        if (it + 2 < NK) fill(it + 2, (it + 2) % 3);

        const unsigned Ab = smem32 + (it % 3) * HT_BYTES;
        const unsigned Bb = smem32 + (HNS + it % 3) * HT_BYTES;

        #pragma unroll
        for (int ks = 0; ks < 4; ks++) {
            unsigned a[4][4], b[4][2];
            #pragma unroll
            for (int mt = 0; mt < 4; mt++) {
                int ch = 2 * ks + a_ch;
                unsigned addr = Ab + arow[mt] * 128 + ((ch ^ (arow[mt] & 7)) << 4);
                ldmx4(a[mt][0], a[mt][1], a[mt][2], a[mt][3], addr);
            }
            #pragma unroll
            for (int p = 0; p < 2; p++) {
                int ch = 2 * ks + b_ch;
                unsigned addr = Bb + brow[p] * 128 + ((ch ^ (brow[p] & 7)) << 4);
                ldmx4(b[2*p][0], b[2*p][1], b[2*p+1][0], b[2*p+1][1], addr);
            }
            #pragma unroll
            for (int mt = 0; mt < 4; mt++)
                #pragma unroll
                for (int nt = 0; nt < 4; nt++)
                    mma_f16(acc[mt][nt], a[mt], b[nt]);
        }
    }

    #pragma unroll
    for (int mt = 0; mt < 4; mt++) {
        long row0 = bm + wm * 64 + mt * 16 + lq;
        long row1 = row0 + 8;
        #pragma unroll
        for (int nt = 0; nt < 4; nt++) {
            int col = bn + wn * 32 + nt * 8 + 2 * lr;
            if (HOUT) {
                __half* C = (__half*)Cv;
                *reinterpret_cast<unsigned*>(&C[row0 * N + col]) =
                    pack_h2(acc[mt][nt][0], acc[mt][nt][1]);
                *reinterpret_cast<unsigned*>(&C[row1 * N + col]) =
                    pack_h2(acc[mt][nt][2], acc[mt][nt][3]);
            } else {
                float* C = (float*)Cv;
                *reinterpret_cast<float2*>(&C[row0 * N + col]) =
                    make_float2(acc[mt][nt][0], acc[mt][nt][1]);
                *reinterpret_cast<float2*>(&C[row1 * N + col]) =
                    make_float2(acc[mt][nt][2], acc[mt][nt][3]);
            }
        }
    }
}

// ---------------------------------------------------------------------------
// FP16 flash attention, column-split warp pairs, 2 CTAs/SM.
// Grid (S/64, H, B), 256 threads (8 warps). Warp w: pair p=w&3 (rows p*16..),
// half hf=w>>2 (score cols hf*32.., output cols hf*64..).
// Smem: Q 16K | K 2x16K | V 2x16K | P 8K | X/Y exchange 1K  (~90KB)
// ---------------------------------------------------------------------------
#define AQ_OFF 0
#define AK_OFF 16384
#define AV_OFF 49152
#define AP_OFF 81920
#define AX_OFF 90112
#define AY_OFF 90624
#define ATTN_SMEM_BYTES 91648

__device__ __forceinline__ float red_max4(float v) {
    v = fmaxf(v, __shfl_xor_sync(0xffffffffu, v, 1));
    v = fmaxf(v, __shfl_xor_sync(0xffffffffu, v, 2));
    return v;
}
__device__ __forceinline__ float red_sum4(float v) {
    v += __shfl_xor_sync(0xffffffffu, v, 1);
    v += __shfl_xor_sync(0xffffffffu, v, 2);
    return v;
}
__device__ __forceinline__ int sw256(int r, int c16) {
    return (c16 & 8) | ((c16 ^ r) & 7);
}

__global__ __launch_bounds__(256, 2) void attn_h_kernel()
{
    extern __shared__ char smc[];
    char* Qs = smc + AQ_OFF;
    char* Ps = smc + AP_OFF;
    float* Xs = reinterpret_cast<float*>(smc + AX_OFF);  // [pair][half][2][8]
    float* Ys = reinterpret_cast<float*>(smc + AY_OFF);
    const unsigned smem32 = (unsigned)__cvta_generic_to_shared(smc);

    const int qt = (int)(gridDim.x - 1) - blockIdx.x;   // 64-row q tile
    const int h  = blockIdx.y;
    const int b  = blockIdx.z;
    const int kvh = h / REP_;

    const int tid  = threadIdx.x;
    const int lane = tid & 31;
    const int w    = tid >> 5;
    const int p    = w & 3;       // row pair
    const int hf   = w >> 2;      // column half
    const int lq   = lane >> 2;
    const int lr   = lane & 3;

    const int a_rl = (lane & 7) + ((lane & 8) ? 8 : 0);
    const int a_ch = lane >> 4;
    const int b_rl = (lane & 7) + ((lane & 16) ? 8 : 0);
    const int b_ch = (lane >> 3) & 1;

    const int nkt = qt + 1;

    const long rowbase = (long)(b * S_);
    const int qcol = h * 128;
    const int kcol = 2048 + kvh * 128;
    const int vcol = 2560 + kvh * 128;

    auto load_kv = [&](int t) {
        char* Kd = smc + AK_OFF + (t & 1) * 16384;
        char* Vd = smc + AV_OFF + (t & 1) * 16384;
        #pragma unroll
        for (int l = 0; l < 4; l++) {
            int i = tid + l * 256;
            int r = i >> 4, c16 = i & 15;
            int dst = r * 256 + (sw256(r & 7, c16) << 4);
            cp16(Kd + dst, &g_qkv[(rowbase + t * 64 + r) * QKV_N + kcol + c16 * 8]);
            cp16(Vd + dst, &g_qkv[(rowbase + t * 64 + r) * QKV_N + vcol + c16 * 8]);
        }
        CP_COMMIT();
    };

    // prologue: Q (64 rows) + KV(0)
    #pragma unroll
    for (int l = 0; l < 4; l++) {
        int i = tid + l * 256;
        int r = i >> 4, c16 = i & 15;
        cp16(Qs + r * 256 + (sw256(r & 7, c16) << 4),
             &g_qkv[(rowbase + qt * 64 + r) * QKV_N + qcol + c16 * 8]);
    }
    load_kv(0);

    float o[8][4];
    #pragma unroll
    for (int nt = 0; nt < 8; nt++)
        #pragma unroll
        for (int j = 0; j < 4; j++) o[nt][j] = 0.f;
    float m0 = -1e30f, m1 = -1e30f, l0 = 0.f, l1 = 0.f;

    const int qrow  = p * 16 + lq;
    const int aqrow = p * 16 + a_rl;
    const int vt = lane >> 3;
    const int vl = lane & 7;
    const int xbase = (p * 2 + hf) * 16;          // this warp's exchange slot
    const int obase = (p * 2 + (1 - hf)) * 16;    // partner's slot

    for (int kt = 0; kt < nkt; kt++) {
        CP_WAIT(0);
        __syncthreads();
        if (kt + 1 < nkt) load_kv(kt + 1);

        const unsigned Kb = smem32 + AK_OFF + (kt & 1) * 16384;
        const unsigned Vb = smem32 + AV_OFF + (kt & 1) * 16384;
        const unsigned Qb = smem32 + AQ_OFF;

        // ---- scores: 16 rows x 32 cols (this warp's half) ----
        float sacc[4][4];
        #pragma unroll
        for (int nt = 0; nt < 4; nt++)
            #pragma unroll
            for (int j = 0; j < 4; j++) sacc[nt][j] = 0.f;

        #pragma unroll
        for (int ks = 0; ks < 8; ks++) {
            unsigned a[4];
            {
                int ch = 2 * ks + a_ch;
                unsigned addr = Qb + aqrow * 256 + (sw256(aqrow & 7, ch) << 4);
                ldmx4(a[0], a[1], a[2], a[3], addr);
            }
            #pragma unroll
            for (int p2 = 0; p2 < 2; p2++) {
                int row = hf * 32 + p2 * 16 + b_rl;
                int ch = 2 * ks + b_ch;
                unsigned addr = Kb + row * 256 + (sw256(row & 7, ch) << 4);
                unsigned b0[2], b1[2];
                ldmx4(b0[0], b0[1], b1[0], b1[1], addr);
                mma_f16(sacc[2*p2],     a, b0);
                mma_f16(sacc[2*p2 + 1], a, b1);
            }
        }

        // ---- causal mask (diagonal tile only) ----
        if (kt == qt) {
            int r0 = qt * 64 + qrow;
            int r1 = r0 + 8;
            #pragma unroll
            for (int nt = 0; nt < 4; nt++) {
                int c = kt * 64 + hf * 32 + nt * 8 + 2 * lr;
                if (c     > r0) sacc[nt][0] = -1e30f;
                if (c + 1 > r0) sacc[nt][1] = -1e30f;
                if (c     > r1) sacc[nt][2] = -1e30f;
                if (c + 1 > r1) sacc[nt][3] = -1e30f;
            }
        }

        // ---- partial row max over this half's 32 cols ----
        float mt0 = -1e30f, mt1 = -1e30f;
        #pragma unroll
        for (int nt = 0; nt < 4; nt++) {
            mt0 = fmaxf(mt0, fmaxf(sacc[nt][0], sacc[nt][1]));
            mt1 = fmaxf(mt1, fmaxf(sacc[nt][2], sacc[nt][3]));
        }
        mt0 = red_max4(mt0);
        mt1 = red_max4(mt1);
        if (lr == 0) {
            Xs[xbase + lq] = mt0;
            Xs[xbase + 8 + lq] = mt1;
        }
        __syncthreads();
        mt0 = fmaxf(mt0, Xs[obase + lq]);
        mt1 = fmaxf(mt1, Xs[obase + 8 + lq]);

        float mn0 = fmaxf(m0, mt0), mn1 = fmaxf(m1, mt1);
        float alpha0 = ex2f(m0 - mn0), alpha1 = ex2f(m1 - mn1);

        float rs0 = 0.f, rs1 = 0.f;
        #pragma unroll
        for (int nt = 0; nt < 4; nt++) {
            sacc[nt][0] = ex2f(sacc[nt][0] - mn0);
            sacc[nt][1] = ex2f(sacc[nt][1] - mn0);
            sacc[nt][2] = ex2f(sacc[nt][2] - mn1);
            sacc[nt][3] = ex2f(sacc[nt][3] - mn1);
            rs0 += sacc[nt][0] + sacc[nt][1];
            rs1 += sacc[nt][2] + sacc[nt][3];
        }
        rs0 = red_sum4(rs0);
        rs1 = red_sum4(rs1);

        // ---- store P half + exchange partial sums ----
        #pragma unroll
        for (int nt = 0; nt < 4; nt++) {
            int c16p = hf * 4 + nt;
            int sw0 = ((c16p ^ (qrow & 7)) & 7) << 4;
            int sw1 = ((c16p ^ ((qrow + 8) & 7)) & 7) << 4;
            *reinterpret_cast<unsigned*>(Ps + qrow * 128 + sw0 + 4 * lr) =
                pack_h2(sacc[nt][0], sacc[nt][1]);
            *reinterpret_cast<unsigned*>(Ps + (qrow + 8) * 128 + sw1 + 4 * lr) =
                pack_h2(sacc[nt][2], sacc[nt][3]);
        }
        if (lr == 0) {
            Ys[xbase + lq] = rs0;
            Ys[xbase + 8 + lq] = rs1;
        }
        __syncthreads();
        rs0 += Ys[obase + lq];
        rs1 += Ys[obase + 8 + lq];

        l0 = l0 * alpha0 + rs0;
        l1 = l1 * alpha1 + rs1;
        m0 = mn0; m1 = mn1;

        #pragma unroll
        for (int nt = 0; nt < 8; nt++) {
            o[nt][0] *= alpha0; o[nt][1] *= alpha0;
            o[nt][2] *= alpha1; o[nt][3] *= alpha1;
        }

        // ---- O += P V (full P rows, this half's 64 V cols) ----
        const unsigned Pb = smem32 + AP_OFF;
        #pragma unroll
        for (int ks = 0; ks < 4; ks++) {
            unsigned a[4];
            {
                int ch = 2 * ks + a_ch;
                unsigned addr = Pb + aqrow * 128 + (((ch ^ (aqrow & 7)) & 7) << 4);
                ldmx4(a[0], a[1], a[2], a[3], addr);
            }
            const int vrow = ks * 16 + ((vt & 1) << 3) + vl;
            #pragma unroll
            for (int nt2 = 0; nt2 < 4; nt2++) {
                int c16 = hf * 8 + 2 * nt2 + (vt >> 1);
                unsigned addr = Vb + vrow * 256 + (sw256(vl, c16) << 4);
                unsigned v0, v1, v2, v3;
                ldmx4_trans(v0, v1, v2, v3, addr);
                unsigned b0[2] = {v0, v1};
                unsigned b1[2] = {v2, v3};
                mma_f16(o[2 * nt2],     a, b0);
                mma_f16(o[2 * nt2 + 1], a, b1);
            }
        }
    }

    // ---- epilogue: this half's 64 cols ----
    float inv0 = 1.0f / l0;
    float inv1 = 1.0f / l1;
    long base0 = (rowbase + qt * 64 + qrow) * (H_ * HD_) + qcol + hf * 64;
    long base1 = base0 + (long)8 * (H_ * HD_);
    #pragma unroll
    for (int nt = 0; nt < 8; nt++) {
        int c = nt * 8 + 2 * lr;
        *reinterpret_cast<unsigned*>(&g_attn[base0 + c]) =
            pack_h2(o[nt][0] * inv0, o[nt][1] * inv0);
        *reinterpret_cast<unsigned*>(&g_attn[base1 + c]) =
            pack_h2(o[nt][2] * inv1, o[nt][3] * inv1);
    }
}

// ---------------------------------------------------------------------------
extern "C" void kernel_launch(void* const* d_in, const int* in_sizes, int n_in,
                              void* d_out, int out_size)
{
    const float* x  = (const float*)d_in[0];
    const float* Wq = (const float*)d_in[1];
    const float* Wk = (const float*)d_in[2];
    const float* Wv = (const float*)d_in[3];
    const float* Wo = (const float*)d_in[4];
    float* out = (float*)d_out;

    __half *xh, *wqkv, *woh, *qkv, *attn;
    cudaGetSymbolAddress((void**)&xh,   g_xh);
    cudaGetSymbolAddress((void**)&wqkv, g_wqkv);
    cudaGetSymbolAddress((void**)&woh,  g_woh);
    cudaGetSymbolAddress((void**)&qkv,  g_qkv);
    cudaGetSymbolAddress((void**)&attn, g_attn);

    const int M = B_ * S_;   // 4096

    prep_all_kernel<<<dim3(64, 296), dim3(32, 8)>>>(x, Wq, Wk, Wv, Wo);

    cudaFuncSetAttribute(h_gemm_kernel<true>,
                         cudaFuncAttributeMaxDynamicSharedMemorySize, HSM_TOTAL);
    cudaFuncSetAttribute(h_gemm_kernel<false>,
                         cudaFuncAttributeMaxDynamicSharedMemorySize, HSM_TOTAL);

    // fused QKV projection
    h_gemm_kernel<true><<<dim3(QKV_N/128, M/128), 256, HSM_TOTAL>>>(
        xh, wqkv, qkv, M, QKV_N, D_);

    // RoPE
    rope_qkv_kernel<<<(M * 20 * 16)/256, 256>>>();

    // Flash attention (column-split, 2 CTAs/SM)
    cudaFuncSetAttribute(attn_h_kernel,
                         cudaFuncAttributeMaxDynamicSharedMemorySize, ATTN_SMEM_BYTES);
    attn_h_kernel<<<dim3(S_/64, H_, B_), 256, ATTN_SMEM_BYTES>>>();

    // Output projection (fp32 out)
    h_gemm_kernel<false><<<dim3(D_/128, M/128), 256, HSM_TOTAL>>>(
        attn, woh, out, M, D_, D_);
}

// round 17
// speedup vs baseline: 1.0492x; 1.0217x over previous
#include <cuda_runtime.h>
#include <cuda_fp16.h>
#include <math.h>
#include <stdint.h>

#define B_ 2
#define S_ 2048
#define D_ 2048
#define H_ 16
#define KVH_ 4
#define HD_ 128
#define REP_ (H_/KVH_)
#define QKV_N 3072          // 2048 Q | 512 K | 512 V
#define SCLF 0.12752934082f  // log2e / sqrt(128)

// Scratch (device globals: allocation-free)
__device__ __half g_xh   [B_*S_*D_];
__device__ __half g_wqkv [QKV_N*D_];       // [N,K] fused Q|K|V weights
__device__ __half g_woh  [D_*H_*HD_];      // [N,K]
__device__ __half g_qkv  [B_*S_*QKV_N];    // fused projections
__device__ __half g_attn [B_*S_*H_*HD_];
__device__ float2 g_ropetab[S_*64];

// ---------------------------------------------------------------------------
// helpers
// ---------------------------------------------------------------------------
__device__ __forceinline__ float ex2f(float x) {
    float r;
    asm("ex2.approx.ftz.f32 %0, %1;" : "=f"(r) : "f"(x));
    return r;
}
__device__ __forceinline__ void mma_f16(
    float* c, const unsigned* a, const unsigned* b)
{
    asm volatile(
        "mma.sync.aligned.m16n8k16.row.col.f32.f16.f16.f32 "
        "{%0,%1,%2,%3}, {%4,%5,%6,%7}, {%8,%9}, {%0,%1,%2,%3};"
        : "+f"(c[0]), "+f"(c[1]), "+f"(c[2]), "+f"(c[3])
        : "r"(a[0]), "r"(a[1]), "r"(a[2]), "r"(a[3]),
          "r"(b[0]), "r"(b[1]));
}
__device__ __forceinline__ void cp16(void* s, const void* g) {
    unsigned sa = (unsigned)__cvta_generic_to_shared(s);
    asm volatile("cp.async.cg.shared.global [%0], [%1], 16;" :: "r"(sa), "l"(g));
}
#define CP_COMMIT()  asm volatile("cp.async.commit_group;")
#define CP_WAIT(n)   asm volatile("cp.async.wait_group %0;" :: "n"(n))

__device__ __forceinline__ void ldmx4(
    unsigned& r0, unsigned& r1, unsigned& r2, unsigned& r3, unsigned addr)
{
    asm volatile(
        "ldmatrix.sync.aligned.m8n8.x4.shared.b16 {%0,%1,%2,%3}, [%4];"
        : "=r"(r0), "=r"(r1), "=r"(r2), "=r"(r3) : "r"(addr));
}
__device__ __forceinline__ void ldmx4_trans(
    unsigned& r0, unsigned& r1, unsigned& r2, unsigned& r3, unsigned addr)
{
    asm volatile(
        "ldmatrix.sync.aligned.m8n8.x4.trans.shared.b16 {%0,%1,%2,%3}, [%4];"
        : "=r"(r0), "=r"(r1), "=r"(r2), "=r"(r3) : "r"(addr));
}
__device__ __forceinline__ unsigned pack_h2(float lo, float hi) {
    __half2 h = __floats2half2_rn(lo, hi);
    return *reinterpret_cast<unsigned*>(&h);
}

// ---------------------------------------------------------------------------
// prep (ONE launch, block 32x8)
// ---------------------------------------------------------------------------
__global__ void prep_all_kernel(const float* __restrict__ x,
                                const float* __restrict__ Wq,
                                const float* __restrict__ Wk,
                                const float* __restrict__ Wv,
                                const float* __restrict__ Wo)
{
    const int yb = blockIdx.y;
    if (yb < 160) {
        __shared__ float t[32][33];
        const float* in; __half* out; int N; int n0;
        if (yb < 64)       { in = Wq; out = g_wqkv;             N = 2048; n0 = yb * 32; }
        else if (yb < 80)  { in = Wk; out = g_wqkv + 2048 * D_; N = 512;  n0 = (yb - 64) * 32; }
        else if (yb < 96)  { in = Wv; out = g_wqkv + 2560 * D_; N = 512;  n0 = (yb - 80) * 32; }
        else               { in = Wo; out = g_woh;              N = 2048; n0 = (yb - 96) * 32; }
        const int k0 = blockIdx.x * 32;
        const int tx = threadIdx.x, ty = threadIdx.y;
        #pragma unroll
        for (int i = 0; i < 32; i += 8)
            t[ty + i][tx] = in[(long)(k0 + ty + i) * N + n0 + tx];
        __syncthreads();
        #pragma unroll
        for (int i = 0; i < 32; i += 8)
            out[(long)(n0 + ty + i) * 2048 + k0 + tx] = __float2half_rn(t[tx][ty + i]);
    } else {
        const int lin = (yb - 160) * 64 + blockIdx.x;       // 0..8703
        const int tid = threadIdx.y * 32 + threadIdx.x;
        if (lin < 8192) {
            int i = lin * 256 + tid;
            float4 v = reinterpret_cast<const float4*>(x)[i];
            uint2 u;
            u.x = pack_h2(v.x, v.y);
            u.y = pack_h2(v.z, v.w);
            reinterpret_cast<uint2*>(g_xh)[i] = u;
        } else {
            int id = (lin - 8192) * 256 + tid;
            int s = id >> 6, i = id & 63;
            float inv = exp2f(-(float)i * (13.287712379549449f / 64.0f));
            float sn, cs;
            sincosf((float)s * inv, &sn, &cs);
            g_ropetab[id] = make_float2(cs, sn);
        }
    }
}

// ---------------------------------------------------------------------------
// RoPE over fused qkv; Q pre-scaled by log2e/sqrt(HD).
// ---------------------------------------------------------------------------
__global__ void rope_qkv_kernel()
{
    long idx = (long)blockIdx.x * blockDim.x + threadIdx.x;
    int i4 = (int)(idx & 15) * 4;
    long t = idx >> 4;
    int h20 = (int)(t % 20);
    long row = t / 20;
    int s = (int)(row % S_);

    const float scl = (h20 < 16) ? SCLF : 1.0f;
    const int col = (h20 < 16) ? h20 * 128 : 2048 + (h20 - 16) * 128;
    __half* p = g_qkv + row * QKV_N + col;

    uint2 lo = *reinterpret_cast<uint2*>(p + i4);
    uint2 hi = *reinterpret_cast<uint2*>(p + i4 + 64);
    const __half2* lo2 = reinterpret_cast<const __half2*>(&lo);
    const __half2* hi2 = reinterpret_cast<const __half2*>(&hi);

    uint2 olo, ohi;
    unsigned* polo = reinterpret_cast<unsigned*>(&olo);
    unsigned* pohi = reinterpret_cast<unsigned*>(&ohi);
    #pragma unroll
    for (int j = 0; j < 2; j++) {
        float2 ta = g_ropetab[s * 64 + i4 + 2*j];
        float2 tb = g_ropetab[s * 64 + i4 + 2*j + 1];
        float x1a = __low2float(lo2[j]),  x1b = __high2float(lo2[j]);
        float x2a = __low2float(hi2[j]),  x2b = __high2float(hi2[j]);
        polo[j] = pack_h2((x1a * ta.x - x2a * ta.y) * scl,
                          (x1b * tb.x - x2b * tb.y) * scl);
        pohi[j] = pack_h2((x2a * ta.x + x1a * ta.y) * scl,
                          (x2b * tb.x + x1b * tb.y) * scl);
    }
    *reinterpret_cast<uint2*>(p + i4)      = olo;
    *reinterpret_cast<uint2*>(p + i4 + 64) = ohi;
}

// ---------------------------------------------------------------------------
// FP16 GEMM (unchanged R14 winner)
// ---------------------------------------------------------------------------
#define HT_BYTES (128*128)
#define HNS 3
#define HSM_TOTAL (2*HNS*HT_BYTES)   // 98304

template<bool HOUT>
__global__ __launch_bounds__(256) void h_gemm_kernel(
    const __half* __restrict__ A, const __half* __restrict__ Bt,
    void* __restrict__ Cv, int M, int N, int K)
{
    extern __shared__ char smem[];
    char* AsBase = smem;
    char* BsBase = smem + HNS * HT_BYTES;
    const unsigned smem32 = (unsigned)__cvta_generic_to_shared(smem);

    const int tid  = threadIdx.x;
    const int lane = tid & 31;
    const int warp = tid >> 5;
    const int wm   = warp >> 2;
    const int wn   = warp & 3;
    const int bm   = blockIdx.y * 128;
    const int bn   = blockIdx.x * 128;
    const int lq = lane >> 2;
    const int lr = lane & 3;

    const int a_rl = (lane & 7) + ((lane & 8) ? 8 : 0);
    const int a_ch = lane >> 4;
    const int b_rl = (lane & 7) + ((lane & 16) ? 8 : 0);
    const int b_ch = (lane >> 3) & 1;

    float acc[4][4][4];
    #pragma unroll
    for (int mt = 0; mt < 4; mt++)
        #pragma unroll
        for (int nt = 0; nt < 4; nt++)
            #pragma unroll
            for (int i = 0; i < 4; i++) acc[mt][nt][i] = 0.f;

    const int NK = K >> 6;

    auto fill = [&](int j, int s) {
        char* As = AsBase + s * HT_BYTES;
        char* Bs = BsBase + s * HT_BYTES;
        const __half* Ag = A  + (long)bm * K + j * 64;
        const __half* Bg = Bt + (long)bn * K + j * 64;
        #pragma unroll
        for (int l = 0; l < 4; l++) {
            int idx = tid + l * 256;
            int r = idx >> 3, c8 = idx & 7;
            int dst = r * 128 + ((c8 ^ (r & 7)) << 4);
            cp16(As + dst, Ag + (long)r * K + c8 * 8);
            cp16(Bs + dst, Bg + (long)r * K + c8 * 8);
        }
        CP_COMMIT();
    };

    fill(0, 0);
    if (NK > 1) fill(1, 1);

    int arow[4], brow[2];
    #pragma unroll
    for (int mt = 0; mt < 4; mt++) arow[mt] = wm * 64 + mt * 16 + a_rl;
    #pragma unroll
    for (int p = 0; p < 2; p++) brow[p] = wn * 32 + p * 16 + b_rl;

    for (int it = 0; it < NK; it++) {
        if (it + 1 < NK) { CP_WAIT(1); } else { CP_WAIT(0); }
        __syncthreads();
        if (it + 2 < NK) fill(it + 2, (it + 2) % 3);

        const unsigned Ab = smem32 + (it % 3) * HT_BYTES;
        const unsigned Bb = smem32 + (HNS + it % 3) * HT_BYTES;

        #pragma unroll
        for (int ks = 0; ks < 4; ks++) {
            unsigned a[4][4], b[4][2];
            #pragma unroll
            for (int mt = 0; mt < 4; mt++) {
                int ch = 2 * ks + a_ch;
                unsigned addr = Ab + arow[mt] * 128 + ((ch ^ (arow[mt] & 7)) << 4);
                ldmx4(a[mt][0], a[mt][1], a[mt][2], a[mt][3], addr);
            }
            #pragma unroll
            for (int p = 0; p < 2; p++) {
                int ch = 2 * ks + b_ch;
                unsigned addr = Bb + brow[p] * 128 + ((ch ^ (brow[p] & 7)) << 4);
                ldmx4(b[2*p][0], b[2*p][1], b[2*p+1][0], b[2*p+1][1], addr);
            }
            #pragma unroll
            for (int mt = 0; mt < 4; mt++)
                #pragma unroll
                for (int nt = 0; nt < 4; nt++)
                    mma_f16(acc[mt][nt], a[mt], b[nt]);
        }
    }

    #pragma unroll
    for (int mt = 0; mt < 4; mt++) {
        long row0 = bm + wm * 64 + mt * 16 + lq;
        long row1 = row0 + 8;
        #pragma unroll
        for (int nt = 0; nt < 4; nt++) {
            int col = bn + wn * 32 + nt * 8 + 2 * lr;
            if (HOUT) {
                __half* C = (__half*)Cv;
                *reinterpret_cast<unsigned*>(&C[row0 * N + col]) =
                    pack_h2(acc[mt][nt][0], acc[mt][nt][1]);
                *reinterpret_cast<unsigned*>(&C[row1 * N + col]) =
                    pack_h2(acc[mt][nt][2], acc[mt][nt][3]);
            } else {
                float* C = (float*)Cv;
                *reinterpret_cast<float2*>(&C[row0 * N + col]) =
                    make_float2(acc[mt][nt][0], acc[mt][nt][1]);
                *reinterpret_cast<float2*>(&C[row1 * N + col]) =
                    make_float2(acc[mt][nt][2], acc[mt][nt][3]);
            }
        }
    }
}

// ---------------------------------------------------------------------------
// FP16 flash attention: R14 per-warp layout in a HALF-SIZE CTA.
// 128 threads (4 warps), 64-row Q tile, warp = 16 q rows x full 64 kv cols.
// Smem: Q 16K | K 2x16K | V 2x16K | P 8K = 88KB -> 2 independent CTAs/SM.
// Grid (S/64, H, B) reversed for causal balance.
// ---------------------------------------------------------------------------
#define AQ_OFF 0
#define AK_OFF 16384
#define AV_OFF 49152
#define AP_OFF 81920
#define ATTN_SMEM_BYTES 90112

__device__ __forceinline__ float red_max4(float v) {
    v = fmaxf(v, __shfl_xor_sync(0xffffffffu, v, 1));
    v = fmaxf(v, __shfl_xor_sync(0xffffffffu, v, 2));
    return v;
}
__device__ __forceinline__ float red_sum4(float v) {
    v += __shfl_xor_sync(0xffffffffu, v, 1);
    v += __shfl_xor_sync(0xffffffffu, v, 2);
    return v;
}
__device__ __forceinline__ int sw256(int r, int c16) {
    return (c16 & 8) | ((c16 ^ r) & 7);
}

__global__ __launch_bounds__(128) void attn_h_kernel()
{
    extern __shared__ char smc[];
    char* Qs = smc + AQ_OFF;
    char* Ps = smc + AP_OFF;
    const unsigned smem32 = (unsigned)__cvta_generic_to_shared(smc);

    const int qt = (int)(gridDim.x - 1) - blockIdx.x;   // 64-row q tile
    const int h  = blockIdx.y;
    const int b  = blockIdx.z;
    const int kvh = h / REP_;

    const int tid  = threadIdx.x;
    const int lane = tid & 31;
    const int w    = tid >> 5;          // 0..3
    const int lq   = lane >> 2;
    const int lr   = lane & 3;

    const int a_rl = (lane & 7) + ((lane & 8) ? 8 : 0);
    const int a_ch = lane >> 4;
    const int b_rl = (lane & 7) + ((lane & 16) ? 8 : 0);
    const int b_ch = (lane >> 3) & 1;

    const int nkt = qt + 1;

    const long rowbase = (long)(b * S_);
    const int qcol = h * 128;
    const int kcol = 2048 + kvh * 128;
    const int vcol = 2560 + kvh * 128;

    auto load_kv = [&](int t) {
        char* Kd = smc + AK_OFF + (t & 1) * 16384;
        char* Vd = smc + AV_OFF + (t & 1) * 16384;
        #pragma unroll
        for (int l = 0; l < 8; l++) {
            int i = tid + l * 128;
            int r = i >> 4, c16 = i & 15;
            int dst = r * 256 + (sw256(r & 7, c16) << 4);
            cp16(Kd + dst, &g_qkv[(rowbase + t * 64 + r) * QKV_N + kcol + c16 * 8]);
            cp16(Vd + dst, &g_qkv[(rowbase + t * 64 + r) * QKV_N + vcol + c16 * 8]);
        }
        CP_COMMIT();
    };

    // prologue: Q (64 rows) + KV(0)
    #pragma unroll
    for (int l = 0; l < 8; l++) {
        int i = tid + l * 128;
        int r = i >> 4, c16 = i & 15;
        cp16(Qs + r * 256 + (sw256(r & 7, c16) << 4),
             &g_qkv[(rowbase + qt * 64 + r) * QKV_N + qcol + c16 * 8]);
    }
    load_kv(0);

    float o[16][4];
    #pragma unroll
    for (int nt = 0; nt < 16; nt++)
        #pragma unroll
        for (int j = 0; j < 4; j++) o[nt][j] = 0.f;
    float m0 = -1e30f, m1 = -1e30f, l0 = 0.f, l1 = 0.f;

    const int qrow = w * 16 + lq;
    const int aqrow = w * 16 + a_rl;
    const int vt = lane >> 3;
    const int vl = lane & 7;

    for (int kt = 0; kt < nkt; kt++) {
        CP_WAIT(0);        // group(kt) complete
        __syncthreads();   // visibility + slot (kt+1)&1 free
        if (kt + 1 < nkt) load_kv(kt + 1);   // overlaps compute(kt)

        const unsigned Kb = smem32 + AK_OFF + (kt & 1) * 16384;
        const unsigned Vb = smem32 + AV_OFF + (kt & 1) * 16384;
        const unsigned Qb = smem32 + AQ_OFF;

        // ---- scores: S = Q K^T (log2e-scaled via Q) ----
        float sacc[8][4];
        #pragma unroll
        for (int nt = 0; nt < 8; nt++)
            #pragma unroll
            for (int j = 0; j < 4; j++) sacc[nt][j] = 0.f;

        #pragma unroll
        for (int ks = 0; ks < 8; ks++) {
            unsigned a[4];
            {
                int ch = 2 * ks + a_ch;
                unsigned addr = Qb + aqrow * 256 + (sw256(aqrow & 7, ch) << 4);
                ldmx4(a[0], a[1], a[2], a[3], addr);
            }
            #pragma unroll
            for (int p = 0; p < 4; p++) {
                int row = p * 16 + b_rl;
                int ch = 2 * ks + b_ch;
                unsigned addr = Kb + row * 256 + (sw256(row & 7, ch) << 4);
                unsigned b0[2], b1[2];
                ldmx4(b0[0], b0[1], b1[0], b1[1], addr);
                mma_f16(sacc[2*p],     a, b0);
                mma_f16(sacc[2*p + 1], a, b1);
            }
        }

        // ---- causal mask (diagonal tile only) ----
        if (kt == qt) {
            int r0 = qt * 64 + qrow;
            int r1 = r0 + 8;
            #pragma unroll
            for (int nt = 0; nt < 8; nt++) {
                int c = kt * 64 + nt * 8 + 2 * lr;
                if (c     > r0) sacc[nt][0] = -1e30f;
                if (c + 1 > r0) sacc[nt][1] = -1e30f;
                if (c     > r1) sacc[nt][2] = -1e30f;
                if (c + 1 > r1) sacc[nt][3] = -1e30f;
            }
        }

        // ---- online softmax (base-2) ----
        float mt0 = -1e30f, mt1 = -1e30f;
        #pragma unroll
        for (int nt = 0; nt < 8; nt++) {
            mt0 = fmaxf(mt0, fmaxf(sacc[nt][0], sacc[nt][1]));
            mt1 = fmaxf(mt1, fmaxf(sacc[nt][2], sacc[nt][3]));
        }
        mt0 = red_max4(mt0);
        mt1 = red_max4(mt1);
        float mn0 = fmaxf(m0, mt0), mn1 = fmaxf(m1, mt1);
        float alpha0 = ex2f(m0 - mn0), alpha1 = ex2f(m1 - mn1);

        float rs0 = 0.f, rs1 = 0.f;
        #pragma unroll
        for (int nt = 0; nt < 8; nt++) {
            sacc[nt][0] = ex2f(sacc[nt][0] - mn0);
            sacc[nt][1] = ex2f(sacc[nt][1] - mn0);
            sacc[nt][2] = ex2f(sacc[nt][2] - mn1);
            sacc[nt][3] = ex2f(sacc[nt][3] - mn1);
            rs0 += sacc[nt][0] + sacc[nt][1];
            rs1 += sacc[nt][2] + sacc[nt][3];
        }
        rs0 = red_sum4(rs0);
        rs1 = red_sum4(rs1);
        l0 = l0 * alpha0 + rs0;
        l1 = l1 * alpha1 + rs1;
        m0 = mn0; m1 = mn1;

        #pragma unroll
        for (int nt = 0; nt < 16; nt++) {
            o[nt][0] *= alpha0; o[nt][1] *= alpha0;
            o[nt][2] *= alpha1; o[nt][3] *= alpha1;
        }

        // ---- store P (per-warp private rows) ----
        #pragma unroll
        for (int nt = 0; nt < 8; nt++) {
            int sw = ((nt ^ lq) & 7) << 4;
            *reinterpret_cast<unsigned*>(Ps + qrow * 128 + sw + 4 * lr) =
                pack_h2(sacc[nt][0], sacc[nt][1]);
            *reinterpret_cast<unsigned*>(Ps + (qrow + 8) * 128 + sw + 4 * lr) =
                pack_h2(sacc[nt][2], sacc[nt][3]);
        }
        __syncwarp();

        // ---- O += P V ----
        const unsigned Pb = smem32 + AP_OFF;
        #pragma unroll
        for (int ks = 0; ks < 4; ks++) {
            unsigned a[4];
            {
                int ch = 2 * ks + a_ch;
                unsigned addr = Pb + aqrow * 128 + (((ch ^ (aqrow & 7)) & 7) << 4);
                ldmx4(a[0], a[1], a[2], a[3], addr);
            }
            const int vrow = ks * 16 + ((vt & 1) << 3) + vl;
            #pragma unroll
            for (int ntt = 0; ntt < 8; ntt++) {
                int c16 = 2 * ntt + (vt >> 1);
                unsigned addr = Vb + vrow * 256 + (sw256(vl, c16) << 4);
                unsigned v0, v1, v2, v3;
                ldmx4_trans(v0, v1, v2, v3, addr);
                unsigned b0[2] = {v0, v1};
                unsigned b1[2] = {v2, v3};
                mma_f16(o[2 * ntt],     a, b0);
                mma_f16(o[2 * ntt + 1], a, b1);
            }
        }
    }

    // ---- epilogue ----
    float inv0 = 1.0f / l0;
    float inv1 = 1.0f / l1;
    long base0 = (rowbase + qt * 64 + qrow) * (H_ * HD_) + qcol;
    long base1 = base0 + (long)8 * (H_ * HD_);
    #pragma unroll
    for (int nt = 0; nt < 16; nt++) {
        int c = nt * 8 + 2 * lr;
        *reinterpret_cast<unsigned*>(&g_attn[base0 + c]) =
            pack_h2(o[nt][0] * inv0, o[nt][1] * inv0);
        *reinterpret_cast<unsigned*>(&g_attn[base1 + c]) =
            pack_h2(o[nt][2] * inv1, o[nt][3] * inv1);
    }
}

// ---------------------------------------------------------------------------
extern "C" void kernel_launch(void* const* d_in, const int* in_sizes, int n_in,
                              void* d_out, int out_size)
{
    const float* x  = (const float*)d_in[0];
    const float* Wq = (const float*)d_in[1];
    const float* Wk = (const float*)d_in[2];
    const float* Wv = (const float*)d_in[3];
    const float* Wo = (const float*)d_in[4];
    float* out = (float*)d_out;

    __half *xh, *wqkv, *woh, *qkv, *attn;
    cudaGetSymbolAddress((void**)&xh,   g_xh);
    cudaGetSymbolAddress((void**)&wqkv, g_wqkv);
    cudaGetSymbolAddress((void**)&woh,  g_woh);
    cudaGetSymbolAddress((void**)&qkv,  g_qkv);
    cudaGetSymbolAddress((void**)&attn, g_attn);

    const int M = B_ * S_;   // 4096

    prep_all_kernel<<<dim3(64, 296), dim3(32, 8)>>>(x, Wq, Wk, Wv, Wo);

    cudaFuncSetAttribute(h_gemm_kernel<true>,
                         cudaFuncAttributeMaxDynamicSharedMemorySize, HSM_TOTAL);
    cudaFuncSetAttribute(h_gemm_kernel<false>,
                         cudaFuncAttributeMaxDynamicSharedMemorySize, HSM_TOTAL);

    // fused QKV projection
    h_gemm_kernel<true><<<dim3(QKV_N/128, M/128), 256, HSM_TOTAL>>>(
        xh, wqkv, qkv, M, QKV_N, D_);

    // RoPE
    rope_qkv_kernel<<<(M * 20 * 16)/256, 256>>>();

    // Flash attention (half-size CTAs, 2 independent CTAs/SM)
    cudaFuncSetAttribute(attn_h_kernel,
                         cudaFuncAttributeMaxDynamicSharedMemorySize, ATTN_SMEM_BYTES);
    attn_h_kernel<<<dim3(S_/64, H_, B_), 128, ATTN_SMEM_BYTES>>>();

    // Output projection (fp32 out)
    h_gemm_kernel<false><<<dim3(D_/128, M/128), 256, HSM_TOTAL>>>(
        attn, woh, out, M, D_, D_);
}